// round 11
// baseline (speedup 1.0000x reference)
#include <cuda_runtime.h>
#include <cuda_fp16.h>
#include <mma.h>
#include <cstdint>
using namespace nvcuda;

#define DM 16384
#define DS 512
#define DH 256
#define DG 768
#define DKE 320
#define DE 300
#define DC2 512

__device__ __align__(256) __half g_ehi[(size_t)DM*DKE];
__device__ __align__(256) __half g_wih[2ull*DG*DKE];
__device__ __align__(256) __half g_whh[2ull*DG*DH];
__device__ __align__(256) __half g_mwh[(size_t)DC2*DC2], g_mwl[(size_t)DC2*DC2];
__device__ __align__(256) __half g_proj[2ull*DM*DG];     // fp16, NO bias
__device__ __align__(256) __half g_ppad[2*DG];           // fp16, NO bias
__device__ __align__(256) __half g_hg[2ull*DM*DG];       // fp16, NO bias
__device__ __align__(256) float g_bih[2*DG], g_bhh[2*DG];
__device__ __align__(256) __half g_hhi[2ull*DM*DH], g_hlo[2ull*DM*DH];
__device__ __align__(256) float g_hidden[(size_t)DM*DC2];
__device__ __align__(256) __half g_nhi[(size_t)DM*DC2], g_nlo[(size_t)DM*DC2];
__device__ __align__(256) float g_mlp[(size_t)DM*DC2];
__device__ __align__(256) float g_bns[128*DC2], g_bnq[128*DC2];
__device__ __align__(256) float g_scale[DC2], g_shift[DC2];
__device__ __align__(256) float g_pool[32*DC2];

__device__ __forceinline__ void cp16(void* s, const void* g) {
    unsigned a = (unsigned)__cvta_generic_to_shared(s);
    asm volatile("cp.async.cg.shared.global [%0], [%1], 16;\n" :: "r"(a), "l"(g));
}
__device__ __forceinline__ void spl(float v, __half* hi, __half* lo) {
    __half h = __float2half(v);
    *hi = h; *lo = __float2half(v - __half2float(h));
}
__device__ __forceinline__ float sigf(float x) { return 1.f / (1.f + __expf(-x)); }

// ---------- prep ----------
__global__ void prep_w(const float* wf, const float* hf, const float* wb, const float* hb) {
    int b = blockIdx.x; int dir = b / DG, g = b % DG; int k = threadIdx.x;
    const float* wi = dir ? wb : wf; const float* wh = dir ? hb : hf;
    float v = (k < DE) ? wi[(size_t)g*DE + k] : 0.f;
    g_wih[((size_t)dir*DG + g)*DKE + k] = __float2half(v);
    if (k < DH)
        g_whh[((size_t)dir*DG + g)*DH + k] = __float2half(wh[(size_t)g*DH + k]);
}
__global__ void prep_bias(const float* bif, const float* bib,
                          const float* bhf, const float* bhb) {
    int i = blockIdx.x*256 + threadIdx.x;     // 0..1535
    if (i < DG) { g_bih[i] = bif[i]; g_bhh[i] = bhf[i]; }
    else        { g_bih[i] = bib[i-DG]; g_bhh[i] = bhb[i-DG]; }
}
__global__ void prep_mlp(const float* mw) {
    size_t i = (size_t)blockIdx.x*DC2 + threadIdx.x;
    spl(mw[i], &g_mwh[i], &g_mwl[i]);
}
__global__ void pad_projk(const float* wf, const float* wb, const float* emb) {
    int idx = blockIdx.x;                      // 0..1535
    int dir = idx / DG, g = idx % DG;
    const float* wi = dir ? wb : wf;
    float a = 0.f;
    for (int e = threadIdx.x; e < DE; e += 128) a += wi[(size_t)g*DE + e] * emb[e];
    __shared__ float red[4];
    #pragma unroll
    for (int o = 16; o; o >>= 1) a += __shfl_xor_sync(~0u, a, o);
    if ((threadIdx.x & 31) == 0) red[threadIdx.x >> 5] = a;
    __syncthreads();
    if (threadIdx.x == 0)
        g_ppad[idx] = __float2half(red[0] + red[1] + red[2] + red[3]);
}
__global__ void gather_emb(const int* x, const float* emb) {
    int m = blockIdx.x, k = threadIdx.x;
    int tok = x[m];
    g_ehi[(size_t)m*DKE + k] = __float2half((k < DE) ? emb[(size_t)tok*DE + k] : 0.f);
}

// ---------- 1-term fp16 GEMM: C = A @ B^T, tile 128x128, 3-stage, 2 CTAs/SM ----------
// mode 0: proj = emb @ Wih^T   mode 1: hg = h @ Whh^T     (fp16 output, no bias)
__global__ void __launch_bounds__(256, 2) gemm1(int mode) {
    extern __shared__ __half sm[];
    const int SA = 128*40;                 // one matrix slot (10240 B)
    const int STG = 2*SA;                  // stage: A + B (20480 B); 3 stages = 61440 B
    const __half *Ah, *Bh; __half* Ch; int K, N;
    int z = blockIdx.z;
    if (mode == 0) { Ah = g_ehi; Bh = g_wih + (size_t)z*DG*DKE;
        Ch = g_proj + (size_t)z*DM*DG; K = DKE; N = DG; }
    else { Ah = g_hhi + (size_t)z*DM*DH; Bh = g_whh + (size_t)z*DG*DH;
        Ch = g_hg + (size_t)z*DM*DG; K = DH; N = DG; }
    int m0 = blockIdx.x*128, n0 = blockIdx.y*128, t = threadIdx.x;
    int NK = K >> 5;
    wmma::fragment<wmma::accumulator,16,16,16,float> acc[4][2];
    #pragma unroll
    for (int i = 0; i < 4; ++i)
        #pragma unroll
        for (int j = 0; j < 2; ++j) wmma::fill_fragment(acc[i][j], 0.f);
    auto load = [&](int kc, int st) {
        __half* b = sm + st*STG;
        int k0 = kc*32;
        #pragma unroll
        for (int c = t; c < 512; c += 256) {
            int r = c >> 2, c8 = (c & 3)*8;
            cp16(b +      r*40 + c8, Ah + (size_t)(m0+r)*K + k0 + c8);
            cp16(b + SA + r*40 + c8, Bh + (size_t)(n0+r)*K + k0 + c8);
        }
        asm volatile("cp.async.commit_group;\n");
    };
    int w = t >> 5, wm = w & 1, wn = w >> 1;   // 2(m) x 4(n) warps, warp tile 64x32
    load(0, 0);
    if (NK > 1) load(1, 1);
    for (int kc = 0; kc < NK; ++kc) {
        int st = kc % 3;
        if (kc + 2 < NK) { load(kc+2, (kc+2) % 3); asm volatile("cp.async.wait_group 2;\n"); }
        else if (kc + 1 < NK) { asm volatile("cp.async.wait_group 1;\n"); }
        else { asm volatile("cp.async.wait_group 0;\n"); }
        __syncthreads();
        const __half *pA = sm + st*STG, *pB = pA + SA;
        #pragma unroll
        for (int kk = 0; kk < 32; kk += 16) {
            wmma::fragment<wmma::matrix_a,16,16,16,__half,wmma::row_major> fa[4];
            wmma::fragment<wmma::matrix_b,16,16,16,__half,wmma::col_major> fb[2];
            #pragma unroll
            for (int i = 0; i < 4; ++i)
                wmma::load_matrix_sync(fa[i], pA + (wm*64 + i*16)*40 + kk, 40);
            #pragma unroll
            for (int j = 0; j < 2; ++j)
                wmma::load_matrix_sync(fb[j], pB + (wn*32 + j*16)*40 + kk, 40);
            #pragma unroll
            for (int i = 0; i < 4; ++i)
                #pragma unroll
                for (int j = 0; j < 2; ++j)
                    wmma::mma_sync(acc[i][j], fa[i], fb[j], acc[i][j]);
        }
        __syncthreads();
    }
    // direct fp16 store (accumulator layouts match across element types)
    #pragma unroll
    for (int i = 0; i < 4; ++i)
        #pragma unroll
        for (int j = 0; j < 2; ++j) {
            wmma::fragment<wmma::accumulator,16,16,16,__half> h;
            #pragma unroll
            for (int e = 0; e < h.num_elements; ++e)
                h.x[e] = __float2half(acc[i][j].x[e]);
            wmma::store_matrix_sync(Ch + (size_t)(m0 + wm*64 + i*16)*N + n0 + wn*32 + j*16,
                                    h, N, wmma::mem_row_major);
        }
}

// ---------- 3-term fp16 GEMM for MLP (fp32 out), 2-stage ----------
__global__ void __launch_bounds__(256) gemm_mlp() {
    extern __shared__ __half sm[];
    const int SA = 128*40;
    const int STG = 4*SA;
    const __half *Ah = g_nhi, *Al = g_nlo, *Bh = g_mwh, *Bl = g_mwl;
    float* Cf = g_mlp;
    const int K = DC2, N = DC2;
    int m0 = blockIdx.x*128, n0 = blockIdx.y*128, t = threadIdx.x;
    int NK = K >> 5;
    wmma::fragment<wmma::accumulator,16,16,16,float> acc[4][2];
    #pragma unroll
    for (int i = 0; i < 4; ++i)
        #pragma unroll
        for (int j = 0; j < 2; ++j) wmma::fill_fragment(acc[i][j], 0.f);
    auto load = [&](int kc, int st) {
        __half* b = sm + (size_t)st*STG;
        int k0 = kc*32;
        #pragma unroll
        for (int c = t; c < 512; c += 256) {
            int r = c >> 2, c8 = (c & 3)*8;
            cp16(b +        r*40 + c8, Ah + (size_t)(m0+r)*K + k0 + c8);
            cp16(b +   SA + r*40 + c8, Al + (size_t)(m0+r)*K + k0 + c8);
            cp16(b + 2*SA + r*40 + c8, Bh + (size_t)(n0+r)*K + k0 + c8);
            cp16(b + 3*SA + r*40 + c8, Bl + (size_t)(n0+r)*K + k0 + c8);
        }
        asm volatile("cp.async.commit_group;\n");
    };
    int w = t >> 5, wm = w & 1, wn = w >> 1;
    load(0, 0);
    for (int kc = 0; kc < NK; ++kc) {
        int st = kc & 1;
        if (kc + 1 < NK) { load(kc+1, st^1); asm volatile("cp.async.wait_group 1;\n"); }
        else             { asm volatile("cp.async.wait_group 0;\n"); }
        __syncthreads();
        const __half *pA = sm + (size_t)st*STG, *pAl = pA + SA,
                     *pB = pA + 2*SA, *pBl = pA + 3*SA;
        #pragma unroll
        for (int kk = 0; kk < 32; kk += 16) {
            wmma::fragment<wmma::matrix_a,16,16,16,__half,wmma::row_major> fa[4], fal[4];
            wmma::fragment<wmma::matrix_b,16,16,16,__half,wmma::col_major> fb[2], fbl[2];
            #pragma unroll
            for (int i = 0; i < 4; ++i) {
                wmma::load_matrix_sync(fa[i],  pA  + (wm*64 + i*16)*40 + kk, 40);
                wmma::load_matrix_sync(fal[i], pAl + (wm*64 + i*16)*40 + kk, 40);
            }
            #pragma unroll
            for (int j = 0; j < 2; ++j) {
                wmma::load_matrix_sync(fb[j],  pB  + (wn*32 + j*16)*40 + kk, 40);
                wmma::load_matrix_sync(fbl[j], pBl + (wn*32 + j*16)*40 + kk, 40);
            }
            #pragma unroll
            for (int i = 0; i < 4; ++i)
                #pragma unroll
                for (int j = 0; j < 2; ++j) {
                    wmma::mma_sync(acc[i][j], fa[i],  fb[j],  acc[i][j]);
                    wmma::mma_sync(acc[i][j], fal[i], fb[j],  acc[i][j]);
                    wmma::mma_sync(acc[i][j], fa[i],  fbl[j], acc[i][j]);
                }
        }
        __syncthreads();
    }
    #pragma unroll
    for (int i = 0; i < 4; ++i)
        #pragma unroll
        for (int j = 0; j < 2; ++j)
            wmma::store_matrix_sync(Cf + (size_t)(m0 + wm*64 + i*16)*N + n0 + wn*32 + j*16,
                                    acc[i][j], N, wmma::mem_row_major);
}

// ---------- GRU gate nonlinearity / state update (half2, biases added here) ----------
__global__ void gru_update(int offF, int offB, int use_hg) {
    int m = blockIdx.x, dir = blockIdx.y, c = threadIdx.x;
    int off = dir ? offB : offF;
    int j = (m & (DS - 1)) + off;
    const __half* pr = (j >= 0 && j < DS) ? g_proj + ((size_t)dir*DM + m + off)*DG
                                          : g_ppad + dir*DG;
    int db = dir*DG + 2*c;
    float2 xr = __half22float2(*(const half2*)(pr + 2*c));
    float2 xz = __half22float2(*(const half2*)(pr + DH + 2*c));
    float2 xn = __half22float2(*(const half2*)(pr + 2*DH + 2*c));
    xr.x += g_bih[db];        xr.y += g_bih[db+1];
    xz.x += g_bih[DH+db];     xz.y += g_bih[DH+db+1];
    xn.x += g_bih[2*DH+db];   xn.y += g_bih[2*DH+db+1];
    float2 hr = make_float2(g_bhh[db],      g_bhh[db+1]);
    float2 hz = make_float2(g_bhh[DH+db],   g_bhh[DH+db+1]);
    float2 hn = make_float2(g_bhh[2*DH+db], g_bhh[2*DH+db+1]);
    float2 hold = make_float2(0.f, 0.f);
    size_t hidx = ((size_t)dir*DM + m)*DH + 2*c;
    if (use_hg) {
        const __half* hg = g_hg + ((size_t)dir*DM + m)*DG;
        float2 a = __half22float2(*(const half2*)(hg + 2*c));
        float2 b = __half22float2(*(const half2*)(hg + DH + 2*c));
        float2 d = __half22float2(*(const half2*)(hg + 2*DH + 2*c));
        hr.x += a.x; hr.y += a.y; hz.x += b.x; hz.y += b.y; hn.x += d.x; hn.y += d.y;
        float2 hi = __half22float2(*(const half2*)(g_hhi + hidx));
        float2 lo = __half22float2(*(const half2*)(g_hlo + hidx));
        hold = make_float2(hi.x + lo.x, hi.y + lo.y);
    }
    float r0 = sigf(xr.x + hr.x), r1 = sigf(xr.y + hr.y);
    float z0 = sigf(xz.x + hz.x), z1 = sigf(xz.y + hz.y);
    float n0 = tanhf(xn.x + r0*hn.x), n1 = tanhf(xn.y + r1*hn.y);
    float h0 = (1.f - z0)*n0 + z0*hold.x;
    float h1 = (1.f - z1)*n1 + z1*hold.y;
    __half hi0, lo0, hi1, lo1;
    spl(h0, &hi0, &lo0); spl(h1, &hi1, &lo1);
    *(half2*)(g_hhi + hidx) = __halves2half2(hi0, hi1);
    *(half2*)(g_hlo + hidx) = __halves2half2(lo0, lo1);
}

// ---------- tail ----------
__global__ void concat_stats(const int* x) {
    int blk = blockIdx.x, c = threadIdx.x;
    float s1 = 0, q1 = 0, s2 = 0, q2 = 0;
    for (int r = 0; r < 128; ++r) {
        int m = blk*128 + r;
        float mk = (x[m] > 0) ? 1.f : 0.f;
        size_t i1 = (size_t)m*DH + c, i2 = ((size_t)DM + m)*DH + c;
        float a = (__half2float(g_hhi[i1]) + __half2float(g_hlo[i1])) * mk;
        float b = (__half2float(g_hhi[i2]) + __half2float(g_hlo[i2])) * mk;
        g_hidden[(size_t)m*DC2 + c] = a;
        g_hidden[(size_t)m*DC2 + DH + c] = b;
        s1 += a; q1 += a*a; s2 += b; q2 += b*b;
    }
    g_bns[blk*DC2 + c] = s1;      g_bnq[blk*DC2 + c] = q1;
    g_bns[blk*DC2 + DH + c] = s2; g_bnq[blk*DC2 + DH + c] = q2;
}
__global__ void bn_fin(const float* gam, const float* bet) {
    int c = threadIdx.x;
    float s = 0, q = 0;
    for (int b = 0; b < 128; ++b) { s += g_bns[b*DC2 + c]; q += g_bnq[b*DC2 + c]; }
    float mu = s / (float)DM;
    float var = q / (float)DM - mu*mu;
    float sc = gam[c] * rsqrtf(var + 1e-5f);
    g_scale[c] = sc; g_shift[c] = bet[c] - mu*sc;
}
__global__ void norm_split(const int* x) {
    int m = blockIdx.x, c = threadIdx.x;
    float mk = (x[m] > 0) ? 1.f : 0.f;
    float v = (g_hidden[(size_t)m*DC2 + c] * g_scale[c] + g_shift[c]) * mk;
    spl(v, &g_nhi[(size_t)m*DC2 + c], &g_nlo[(size_t)m*DC2 + c]);
}
__global__ void poolk(const int* x, const float* mb) {
    int b = blockIdx.x, c = threadIdx.x;
    float bias = mb[c], mx = -3.4e38f;
    for (int s = 0; s < DS; ++s) {
        int m = b*DS + s;
        float v = (x[m] > 0) ? g_mlp[(size_t)m*DC2 + c] + bias : -65500.f;
        mx = fmaxf(mx, v);
    }
    g_pool[b*DC2 + c] = mx;
}
__global__ void headk(const float* lw, const float* lb, float* out) {
    int b = blockIdx.x, w = threadIdx.x >> 5, l = threadIdx.x & 31;
    float s = 0;
    for (int i = l; i < DC2; i += 32) s += g_pool[b*DC2 + i] * lw[(size_t)w*DC2 + i];
    #pragma unroll
    for (int o = 16; o; o >>= 1) s += __shfl_xor_sync(~0u, s, o);
    if (!l) out[b*2 + w] = s + lb[w];
}

extern "C" void kernel_launch(void* const* d_in, const int* in_sizes, int n_in,
                              void* d_out, int out_size) {
    const int*   x    = (const int*)d_in[0];
    const float* emb  = (const float*)d_in[5];
    const float* wihf = (const float*)d_in[6];
    const float* whhf = (const float*)d_in[7];
    const float* bihf = (const float*)d_in[8];
    const float* bhhf = (const float*)d_in[9];
    const float* wihb = (const float*)d_in[10];
    const float* whhb = (const float*)d_in[11];
    const float* bihb = (const float*)d_in[12];
    const float* bhhb = (const float*)d_in[13];
    const float* gam  = (const float*)d_in[14];
    const float* bet  = (const float*)d_in[15];
    const float* mw   = (const float*)d_in[16];
    const float* mb   = (const float*)d_in[17];
    const float* lw   = (const float*)d_in[18];
    const float* lb   = (const float*)d_in[19];
    float* out = (float*)d_out;

    cudaFuncSetAttribute(gemm1, cudaFuncAttributeMaxDynamicSharedMemorySize, 61440);
    cudaFuncSetAttribute(gemm_mlp, cudaFuncAttributeMaxDynamicSharedMemorySize, 81920);

    prep_w<<<2*DG, DKE>>>(wihf, whhf, wihb, whhb);
    prep_bias<<<6, 256>>>(bihf, bihb, bhhf, bhhb);
    prep_mlp<<<DC2, DC2>>>(mw);
    pad_projk<<<2*DG, 128>>>(wihf, wihb, emb);
    gather_emb<<<DM, DKE>>>(x, emb);

    gemm1<<<dim3(DM/128, DG/128, 2), 256, 61440>>>(0);   // proj fp16
    gru_update<<<dim3(DM,2), 128>>>(-14, 14, 0);
    for (int i = 1; i < 15; ++i) {
        gemm1<<<dim3(DM/128, DG/128, 2), 256, 61440>>>(1);   // hg fp16
        gru_update<<<dim3(DM,2), 128>>>(i - 14, 14 - i, 1);
    }
    concat_stats<<<128, 256>>>(x);
    bn_fin<<<1, DC2>>>(gam, bet);
    norm_split<<<DM, DC2>>>(x);
    gemm_mlp<<<dim3(DM/128, DC2/128, 1), 256, 81920>>>();
    poolk<<<32, DC2>>>(x, mb);
    headk<<<32, 64>>>(lw, lb, out);
}

// round 14
// speedup vs baseline: 1.3475x; 1.3475x over previous
#include <cuda_runtime.h>
#include <cuda_fp16.h>
#include <mma.h>
#include <cstdint>
using namespace nvcuda;

#define DM 16384
#define DS 512
#define DH 256
#define DG 768
#define DKE 320
#define DE 300
#define DC2 512

__device__ __align__(256) __half g_ehi[(size_t)DM*DKE];
__device__ __align__(256) __half g_wih[2ull*DG*DKE];
__device__ __align__(256) __half g_whh[2ull*DG*DH];
__device__ __align__(256) __half g_mwh[(size_t)DC2*DC2], g_mwl[(size_t)DC2*DC2];
__device__ __align__(256) __half g_proj[2ull*DM*DG];     // fp16, bih folded
__device__ __align__(256) __half g_ppad[2*DG];           // fp16, bih folded
__device__ __align__(256) __half g_hg[2ull*DM*DG];       // fp16, bhh folded
__device__ __align__(256) float g_bih[2*DG], g_bhh[2*DG];
__device__ __align__(256) __half g_hhi[2ull*DM*DH], g_hlo[2ull*DM*DH];
__device__ __align__(256) float g_hidden[(size_t)DM*DC2];
__device__ __align__(256) __half g_nhi[(size_t)DM*DC2], g_nlo[(size_t)DM*DC2];
__device__ __align__(256) float g_mlp[(size_t)DM*DC2];
__device__ __align__(256) float g_bns[128*DC2], g_bnq[128*DC2];
__device__ __align__(256) float g_scale[DC2], g_shift[DC2];
__device__ __align__(256) float g_pool[32*DC2];

__device__ __forceinline__ void cp16(void* s, const void* g) {
    unsigned a = (unsigned)__cvta_generic_to_shared(s);
    asm volatile("cp.async.cg.shared.global [%0], [%1], 16;\n" :: "r"(a), "l"(g));
}
__device__ __forceinline__ void spl(float v, __half* hi, __half* lo) {
    __half h = __float2half(v);
    *hi = h; *lo = __float2half(v - __half2float(h));
}
__device__ __forceinline__ float sigf(float x) { return 1.f / (1.f + __expf(-x)); }

// ---------- mega-prep: one launch does all weight/emb preparation ----------
// grid 19968 x 320 threads:
//   [0,1536)            weight rows (wih/whh fp16) + biases
//   [1536,17920)        emb gather
//   [17920,18432)       MLP weight split
//   [18432,19968)       pad-window projection (dot(Wih_row, emb[0]) + bih)
__global__ void prep_all(const int* x, const float* emb,
                         const float* wf, const float* hf, const float* bif, const float* bhf,
                         const float* wb, const float* hb, const float* bib, const float* bhb,
                         const float* mw) {
    int b = blockIdx.x, t = threadIdx.x;
    if (b < 1536) {
        int dir = b / DG, g = b % DG;
        const float* wi = dir ? wb : wf; const float* wh = dir ? hb : hf;
        float v = (t < DE) ? wi[(size_t)g*DE + t] : 0.f;
        g_wih[((size_t)dir*DG + g)*DKE + t] = __float2half(v);
        if (t < DH)
            g_whh[((size_t)dir*DG + g)*DH + t] = __float2half(wh[(size_t)g*DH + t]);
        if (t == 0) {
            int i = dir*DG + g;
            g_bih[i] = (dir ? bib : bif)[g];
            g_bhh[i] = (dir ? bhb : bhf)[g];
        }
    } else if (b < 17920) {
        int m = b - 1536;
        int tok = x[m];
        g_ehi[(size_t)m*DKE + t] = __float2half((t < DE) ? emb[(size_t)tok*DE + t] : 0.f);
    } else if (b < 18432) {
        int p = b - 17920;
        for (int c = t; c < DC2; c += 320) {
            size_t i = (size_t)p*DC2 + c;
            spl(mw[i], &g_mwh[i], &g_mwl[i]);
        }
    } else {
        int idx = b - 18432;
        int dir = idx / DG, g = idx % DG;
        const float* wi = dir ? wb : wf;
        float a = (t < DE) ? wi[(size_t)g*DE + t] * emb[t] : 0.f;
        __shared__ float red[10];
        #pragma unroll
        for (int o = 16; o; o >>= 1) a += __shfl_xor_sync(~0u, a, o);
        if ((t & 31) == 0) red[t >> 5] = a;
        __syncthreads();
        if (t == 0) {
            float s = 0.f;
            #pragma unroll
            for (int w2 = 0; w2 < 10; ++w2) s += red[w2];
            g_ppad[idx] = __float2half(s + (dir ? bib : bif)[g]);
        }
    }
}

// ---------- 1-term fp16 GEMM: C = A @ B^T, tile 128x128, K-chunk 64, 2-stage ----------
// mode 0: proj = emb @ Wih^T (+bih)   mode 1: hg = h @ Whh^T (+bhh)   fp16 out
__global__ void __launch_bounds__(256) gemm1(int mode) {
    extern __shared__ __half sm[];
    const int SA = 128*72;                 // one matrix slot (18432 B)
    const int STG = 2*SA;                  // stage 36864 B; 2 stages = 73728 B
    const __half *Ah, *Bh; __half* Ch; const float* bias; int K;
    const int N = DG;
    int z = blockIdx.z;
    if (mode == 0) { Ah = g_ehi; Bh = g_wih + (size_t)z*DG*DKE;
        Ch = g_proj + (size_t)z*DM*DG; bias = g_bih + z*DG; K = DKE; }
    else { Ah = g_hhi + (size_t)z*DM*DH; Bh = g_whh + (size_t)z*DG*DH;
        Ch = g_hg + (size_t)z*DM*DG; bias = g_bhh + z*DG; K = DH; }
    int m0 = blockIdx.x*128, n0 = blockIdx.y*128, t = threadIdx.x;
    int NK = K >> 6;                        // 4 (K=256) or 5 (K=320)
    wmma::fragment<wmma::accumulator,16,16,16,float> acc[4][2];
    #pragma unroll
    for (int i = 0; i < 4; ++i)
        #pragma unroll
        for (int j = 0; j < 2; ++j) wmma::fill_fragment(acc[i][j], 0.f);
    auto load = [&](int kc, int st) {
        __half* b = sm + st*STG;
        int k0 = kc*64;
        #pragma unroll
        for (int c = t; c < 1024; c += 256) {
            int r = c >> 3, c8 = (c & 7)*8;
            cp16(b +      r*72 + c8, Ah + (size_t)(m0+r)*K + k0 + c8);
            cp16(b + SA + r*72 + c8, Bh + (size_t)(n0+r)*K + k0 + c8);
        }
        asm volatile("cp.async.commit_group;\n");
    };
    int w = t >> 5, wm = w & 1, wn = w >> 1;   // 2(m) x 4(n) warps, warp tile 64x32
    load(0, 0);
    for (int kc = 0; kc < NK; ++kc) {
        int st = kc & 1;
        if (kc + 1 < NK) { load(kc+1, st^1); asm volatile("cp.async.wait_group 1;\n"); }
        else             { asm volatile("cp.async.wait_group 0;\n"); }
        __syncthreads();
        const __half *pA = sm + st*STG, *pB = pA + SA;
        #pragma unroll
        for (int kk = 0; kk < 64; kk += 16) {
            wmma::fragment<wmma::matrix_a,16,16,16,__half,wmma::row_major> fa[4];
            wmma::fragment<wmma::matrix_b,16,16,16,__half,wmma::col_major> fb[2];
            #pragma unroll
            for (int i = 0; i < 4; ++i)
                wmma::load_matrix_sync(fa[i], pA + (wm*64 + i*16)*72 + kk, 72);
            #pragma unroll
            for (int j = 0; j < 2; ++j)
                wmma::load_matrix_sync(fb[j], pB + (wn*32 + j*16)*72 + kk, 72);
            #pragma unroll
            for (int i = 0; i < 4; ++i)
                #pragma unroll
                for (int j = 0; j < 2; ++j)
                    wmma::mma_sync(acc[i][j], fa[i], fb[j], acc[i][j]);
        }
        __syncthreads();
    }
    // stage through smem, add bias, write fp16 (uint4 = 8 halves)
    float* sC = (float*)sm;                      // 128 x 132 fp32 (67584 B)
    #pragma unroll
    for (int i = 0; i < 4; ++i)
        #pragma unroll
        for (int j = 0; j < 2; ++j)
            wmma::store_matrix_sync(sC + (wm*64 + i*16)*132 + wn*32 + j*16,
                                    acc[i][j], 132, wmma::mem_row_major);
    __syncthreads();
    int r = t >> 1, c0 = (t & 1)*64;
    #pragma unroll
    for (int j = 0; j < 64; j += 8) {
        __half tmp[8];
        #pragma unroll
        for (int k = 0; k < 8; ++k)
            tmp[k] = __float2half(sC[r*132 + c0 + j + k] + bias[n0 + c0 + j + k]);
        *(uint4*)(Ch + (size_t)(m0 + r)*N + n0 + c0 + j) = *(uint4*)tmp;
    }
}

// ---------- 3-term fp16 GEMM for MLP (fp32 out), 2-stage ----------
__global__ void __launch_bounds__(256) gemm_mlp() {
    extern __shared__ __half sm[];
    const int SA = 128*40;
    const int STG = 4*SA;
    const __half *Ah = g_nhi, *Al = g_nlo, *Bh = g_mwh, *Bl = g_mwl;
    float* Cf = g_mlp;
    const int K = DC2, N = DC2;
    int m0 = blockIdx.x*128, n0 = blockIdx.y*128, t = threadIdx.x;
    int NK = K >> 5;
    wmma::fragment<wmma::accumulator,16,16,16,float> acc[4][2];
    #pragma unroll
    for (int i = 0; i < 4; ++i)
        #pragma unroll
        for (int j = 0; j < 2; ++j) wmma::fill_fragment(acc[i][j], 0.f);
    auto load = [&](int kc, int st) {
        __half* b = sm + (size_t)st*STG;
        int k0 = kc*32;
        #pragma unroll
        for (int c = t; c < 512; c += 256) {
            int r = c >> 2, c8 = (c & 3)*8;
            cp16(b +        r*40 + c8, Ah + (size_t)(m0+r)*K + k0 + c8);
            cp16(b +   SA + r*40 + c8, Al + (size_t)(m0+r)*K + k0 + c8);
            cp16(b + 2*SA + r*40 + c8, Bh + (size_t)(n0+r)*K + k0 + c8);
            cp16(b + 3*SA + r*40 + c8, Bl + (size_t)(n0+r)*K + k0 + c8);
        }
        asm volatile("cp.async.commit_group;\n");
    };
    int w = t >> 5, wm = w & 1, wn = w >> 1;
    load(0, 0);
    for (int kc = 0; kc < NK; ++kc) {
        int st = kc & 1;
        if (kc + 1 < NK) { load(kc+1, st^1); asm volatile("cp.async.wait_group 1;\n"); }
        else             { asm volatile("cp.async.wait_group 0;\n"); }
        __syncthreads();
        const __half *pA = sm + (size_t)st*STG, *pAl = pA + SA,
                     *pB = pA + 2*SA, *pBl = pA + 3*SA;
        #pragma unroll
        for (int kk = 0; kk < 32; kk += 16) {
            wmma::fragment<wmma::matrix_a,16,16,16,__half,wmma::row_major> fa[4], fal[4];
            wmma::fragment<wmma::matrix_b,16,16,16,__half,wmma::col_major> fb[2], fbl[2];
            #pragma unroll
            for (int i = 0; i < 4; ++i) {
                wmma::load_matrix_sync(fa[i],  pA  + (wm*64 + i*16)*40 + kk, 40);
                wmma::load_matrix_sync(fal[i], pAl + (wm*64 + i*16)*40 + kk, 40);
            }
            #pragma unroll
            for (int j = 0; j < 2; ++j) {
                wmma::load_matrix_sync(fb[j],  pB  + (wn*32 + j*16)*40 + kk, 40);
                wmma::load_matrix_sync(fbl[j], pBl + (wn*32 + j*16)*40 + kk, 40);
            }
            #pragma unroll
            for (int i = 0; i < 4; ++i)
                #pragma unroll
                for (int j = 0; j < 2; ++j) {
                    wmma::mma_sync(acc[i][j], fa[i],  fb[j],  acc[i][j]);
                    wmma::mma_sync(acc[i][j], fal[i], fb[j],  acc[i][j]);
                    wmma::mma_sync(acc[i][j], fa[i],  fbl[j], acc[i][j]);
                }
        }
        __syncthreads();
    }
    #pragma unroll
    for (int i = 0; i < 4; ++i)
        #pragma unroll
        for (int j = 0; j < 2; ++j)
            wmma::store_matrix_sync(Cf + (size_t)(m0 + wm*64 + i*16)*N + n0 + wn*32 + j*16,
                                    acc[i][j], N, wmma::mem_row_major);
}

// ---------- GRU gate nonlinearity / state update (half2) ----------
__global__ void gru_update(int offF, int offB, int use_hg) {
    int m = blockIdx.x, dir = blockIdx.y, c = threadIdx.x;
    int off = dir ? offB : offF;
    int j = (m & (DS - 1)) + off;
    const __half* pr = (j >= 0 && j < DS) ? g_proj + ((size_t)dir*DM + m + off)*DG
                                          : g_ppad + dir*DG;
    float2 xr = __half22float2(*(const half2*)(pr + 2*c));
    float2 xz = __half22float2(*(const half2*)(pr + DH + 2*c));
    float2 xn = __half22float2(*(const half2*)(pr + 2*DH + 2*c));
    float2 hr, hz, hn;
    float2 hold = make_float2(0.f, 0.f);
    size_t hidx = ((size_t)dir*DM + m)*DH + 2*c;
    if (use_hg) {
        const __half* hg = g_hg + ((size_t)dir*DM + m)*DG;
        hr = __half22float2(*(const half2*)(hg + 2*c));
        hz = __half22float2(*(const half2*)(hg + DH + 2*c));
        hn = __half22float2(*(const half2*)(hg + 2*DH + 2*c));
        float2 hi = __half22float2(*(const half2*)(g_hhi + hidx));
        float2 lo = __half22float2(*(const half2*)(g_hlo + hidx));
        hold = make_float2(hi.x + lo.x, hi.y + lo.y);
    } else {
        int db = dir*DG + 2*c;
        hr = make_float2(g_bhh[db],        g_bhh[db+1]);
        hz = make_float2(g_bhh[DH+db],     g_bhh[DH+db+1]);
        hn = make_float2(g_bhh[2*DH+db],   g_bhh[2*DH+db+1]);
    }
    float r0 = sigf(xr.x + hr.x), r1 = sigf(xr.y + hr.y);
    float z0 = sigf(xz.x + hz.x), z1 = sigf(xz.y + hz.y);
    float n0 = tanhf(xn.x + r0*hn.x), n1 = tanhf(xn.y + r1*hn.y);
    float h0 = (1.f - z0)*n0 + z0*hold.x;
    float h1 = (1.f - z1)*n1 + z1*hold.y;
    __half hi0, lo0, hi1, lo1;
    spl(h0, &hi0, &lo0); spl(h1, &hi1, &lo1);
    *(half2*)(g_hhi + hidx) = __halves2half2(hi0, hi1);
    *(half2*)(g_hlo + hidx) = __halves2half2(lo0, lo1);
}

// ---------- tail ----------
__global__ void concat_stats(const int* x) {
    int blk = blockIdx.x, c = threadIdx.x;
    float s1 = 0, q1 = 0, s2 = 0, q2 = 0;
    for (int r = 0; r < 128; ++r) {
        int m = blk*128 + r;
        float mk = (x[m] > 0) ? 1.f : 0.f;
        size_t i1 = (size_t)m*DH + c, i2 = ((size_t)DM + m)*DH + c;
        float a = (__half2float(g_hhi[i1]) + __half2float(g_hlo[i1])) * mk;
        float b = (__half2float(g_hhi[i2]) + __half2float(g_hlo[i2])) * mk;
        g_hidden[(size_t)m*DC2 + c] = a;
        g_hidden[(size_t)m*DC2 + DH + c] = b;
        s1 += a; q1 += a*a; s2 += b; q2 += b*b;
    }
    g_bns[blk*DC2 + c] = s1;      g_bnq[blk*DC2 + c] = q1;
    g_bns[blk*DC2 + DH + c] = s2; g_bnq[blk*DC2 + DH + c] = q2;
}
__global__ void bn_fin(const float* gam, const float* bet) {
    int c = threadIdx.x;
    float s = 0, q = 0;
    for (int b = 0; b < 128; ++b) { s += g_bns[b*DC2 + c]; q += g_bnq[b*DC2 + c]; }
    float mu = s / (float)DM;
    float var = q / (float)DM - mu*mu;
    float sc = gam[c] * rsqrtf(var + 1e-5f);
    g_scale[c] = sc; g_shift[c] = bet[c] - mu*sc;
}
__global__ void norm_split(const int* x) {
    int m = blockIdx.x, c = threadIdx.x;
    float mk = (x[m] > 0) ? 1.f : 0.f;
    float v = (g_hidden[(size_t)m*DC2 + c] * g_scale[c] + g_shift[c]) * mk;
    spl(v, &g_nhi[(size_t)m*DC2 + c], &g_nlo[(size_t)m*DC2 + c]);
}
__global__ void poolk(const int* x, const float* mb) {
    int b = blockIdx.x, c = threadIdx.x;
    float bias = mb[c], mx = -3.4e38f;
    for (int s = 0; s < DS; ++s) {
        int m = b*DS + s;
        float v = (x[m] > 0) ? g_mlp[(size_t)m*DC2 + c] + bias : -65500.f;
        mx = fmaxf(mx, v);
    }
    g_pool[b*DC2 + c] = mx;
}
__global__ void headk(const float* lw, const float* lb, float* out) {
    int b = blockIdx.x, w = threadIdx.x >> 5, l = threadIdx.x & 31;
    float s = 0;
    for (int i = l; i < DC2; i += 32) s += g_pool[b*DC2 + i] * lw[(size_t)w*DC2 + i];
    #pragma unroll
    for (int o = 16; o; o >>= 1) s += __shfl_xor_sync(~0u, s, o);
    if (!l) out[b*2 + w] = s + lb[w];
}

extern "C" void kernel_launch(void* const* d_in, const int* in_sizes, int n_in,
                              void* d_out, int out_size) {
    const int*   x    = (const int*)d_in[0];
    const float* emb  = (const float*)d_in[5];
    const float* wihf = (const float*)d_in[6];
    const float* whhf = (const float*)d_in[7];
    const float* bihf = (const float*)d_in[8];
    const float* bhhf = (const float*)d_in[9];
    const float* wihb = (const float*)d_in[10];
    const float* whhb = (const float*)d_in[11];
    const float* bihb = (const float*)d_in[12];
    const float* bhhb = (const float*)d_in[13];
    const float* gam  = (const float*)d_in[14];
    const float* bet  = (const float*)d_in[15];
    const float* mw   = (const float*)d_in[16];
    const float* mb   = (const float*)d_in[17];
    const float* lw   = (const float*)d_in[18];
    const float* lb   = (const float*)d_in[19];
    float* out = (float*)d_out;

    cudaFuncSetAttribute(gemm1, cudaFuncAttributeMaxDynamicSharedMemorySize, 73728);
    cudaFuncSetAttribute(gemm_mlp, cudaFuncAttributeMaxDynamicSharedMemorySize, 81920);

    prep_all<<<19968, 320>>>(x, emb, wihf, whhf, bihf, bhhf,
                             wihb, whhb, bihb, bhhb, mw);          // launch 0
    gemm1<<<dim3(DM/128, DG/128, 2), 256, 73728>>>(0);             // launch 1: proj
    gru_update<<<dim3(DM,2), 128>>>(-14, 14, 0);                   // launch 2
    for (int i = 1; i < 15; ++i) {
        gemm1<<<dim3(DM/128, DG/128, 2), 256, 73728>>>(1);         // launch 3 = PROFILED
        gru_update<<<dim3(DM,2), 128>>>(i - 14, 14 - i, 1);
    }
    concat_stats<<<128, 256>>>(x);
    bn_fin<<<1, DC2>>>(gam, bet);
    norm_split<<<DM, DC2>>>(x);
    gemm_mlp<<<dim3(DM/128, DC2/128, 1), 256, 81920>>>();
    poolk<<<32, DC2>>>(x, mb);
    headk<<<32, 64>>>(lw, lb, out);
}